// round 10
// baseline (speedup 1.0000x reference)
#include <cuda_runtime.h>
#include <math.h>
#include <stdint.h>

#define N_NODES   50000
#define N_EDGES   800000
#define NF        96
#define NH        128
#define NC        40
#define CHUNKS    10          // NC / 4 float4 chunks per node row
#define NVEC      (N_NODES * CHUNKS)   // 500000 float4 per node array
#define GROWS     32          // rows per GEMM block

// ---------------- device scratch (static, allocation-free) ----------------
// NOTE: these symbols are ONLY referenced from device code. Passing them as
// host-side kernel arguments silently yields the host shadow address (ATS
// makes it dereferenceable on GB300) — that was the round-9 bug.
__device__ __align__(16) float g_t  [N_NODES * NC];   // norm*feat@M2^T, later hop-2 acc
__device__ __align__(16) float g_acc[N_NODES * NC];   // hop-1 accumulator
__device__ float g_norm[N_NODES];                     // degree, then norm
__device__ float g_M1[NF * NC];                       // transposed: [f][c]
__device__ float g_M2[NF * NC];

// ---------------------------------------------------------------------------
__global__ void k_zero() {
    int i = blockIdx.x * blockDim.x + threadIdx.x;
    if (i < N_NODES * NC) g_acc[i] = 0.0f;
    if (i < N_NODES)      g_norm[i] = 0.0f;
}

__global__ void k_deg(const int* __restrict__ dst) {
    int e = blockIdx.x * blockDim.x + threadIdx.x;
    if (e < N_EDGES) atomicAdd(&g_norm[dst[e]], 1.0f);
}

__global__ void k_norm() {
    int v = blockIdx.x * blockDim.x + threadIdx.x;
    if (v < N_NODES) {
        float d = g_norm[v];
        g_norm[v] = (d > 0.0f) ? rsqrtf(d) : 1.0f;
    }
}

// M1[c,f] = sum_h Wp[c, h]      * W_lin[h, f]
// M2[c,f] = sum_h Wp[c, 128+h]  * W_sgc[h, f]
// stored transposed: gM[f*40 + c]
__global__ void k_weights(const float* __restrict__ Wp,
                          const float* __restrict__ Wsgc,
                          const float* __restrict__ Wlin) {
    int c = blockIdx.x;         // 0..39
    int sel = blockIdx.y;       // 0 -> M1, 1 -> M2
    int f = threadIdx.x;        // 0..95
    const float* wp = Wp + c * 256 + sel * 128;
    const float* W  = sel ? Wsgc : Wlin;
    float acc = 0.0f;
#pragma unroll 8
    for (int h = 0; h < NH; h++)
        acc = fmaf(wp[h], W[h * NF + f], acc);
    (sel ? g_M2 : g_M1)[f * NC + c] = acc;
}

__device__ __forceinline__ void fma4(float4& a, float s, const float4 m) {
    a.x = fmaf(s, m.x, a.x);
    a.y = fmaf(s, m.y, a.y);
    a.z = fmaf(s, m.z, a.z);
    a.w = fmaf(s, m.w, a.w);
}

// Fused dual GEMM:
//   out[v, :] = feat[v, :] @ M1^T          (base term, straight to d_out)
//   g_t[v, :] = norm[v] * (feat[v,:]@M2^T) (pre-scaled propagation input)
// blockDim = (10, 16), 32 rows/block. Each thread: 2 rows x 4 cols x 2 mats.
__global__ void __launch_bounds__(160) k_gemm(const float* __restrict__ feat,
                                              float* __restrict__ out) {
    __shared__ __align__(16) float sF [GROWS * 97];   // padded stride 97
    __shared__ __align__(16) float sM1[NF * NC];
    __shared__ __align__(16) float sM2[NF * NC];

    const int tid = threadIdx.y * 10 + threadIdx.x;
    for (int i = tid; i < NF * NC; i += 160) { sM1[i] = g_M1[i]; sM2[i] = g_M2[i]; }

    const int row0 = blockIdx.x * GROWS;
    for (int i = tid; i < GROWS * NF; i += 160) {
        int r = i / NF, f = i - r * NF;
        int v = row0 + r;
        sF[r * 97 + f] = (v < N_NODES) ? feat[(size_t)v * NF + f] : 0.0f;
    }
    __syncthreads();

    const int cx = threadIdx.x;            // col group: cols 4*cx .. 4*cx+3
    const int r0 = threadIdx.y * 2;        // rows r0, r0+1

    float4 a1r0 = make_float4(0, 0, 0, 0), a1r1 = a1r0;
    float4 a2r0 = a1r0, a2r1 = a1r0;

#pragma unroll 8
    for (int f = 0; f < NF; f++) {
        const float4 m1 = *reinterpret_cast<const float4*>(sM1 + f * NC + cx * 4);
        const float4 m2 = *reinterpret_cast<const float4*>(sM2 + f * NC + cx * 4);
        const float f0 = sF[r0 * 97 + f];
        const float f1 = sF[(r0 + 1) * 97 + f];
        fma4(a1r0, f0, m1); fma4(a2r0, f0, m2);
        fma4(a1r1, f1, m1); fma4(a2r1, f1, m2);
    }

    const int v0 = row0 + r0;
    if (v0 < N_NODES) {
        float n = g_norm[v0];
        *reinterpret_cast<float4*>(out + (size_t)v0 * NC + cx * 4) = a1r0;
        float4 t = a2r0; t.x *= n; t.y *= n; t.z *= n; t.w *= n;
        *reinterpret_cast<float4*>(g_t + (size_t)v0 * NC + cx * 4) = t;
    }
    const int v1 = v0 + 1;
    if (v1 < N_NODES) {
        float n = g_norm[v1];
        *reinterpret_cast<float4*>(out + (size_t)v1 * NC + cx * 4) = a1r1;
        float4 t = a2r1; t.x *= n; t.y *= n; t.z *= n; t.w *= n;
        *reinterpret_cast<float4*>(g_t + (size_t)v1 * NC + cx * 4) = t;
    }
}

__device__ __forceinline__ void red4(float* p, const float4 v) {
    asm volatile("red.global.add.v4.f32 [%0], {%1, %2, %3, %4};"
                 :: "l"(p), "f"(v.x), "f"(v.y), "f"(v.z), "f"(v.w)
                 : "memory");
}

// Hop 1: g_acc[dst] += g_t[src]. Symbols referenced in DEVICE code (the fix).
__global__ void k_scatter1(const int* __restrict__ src,
                           const int* __restrict__ dst) {
    int tid = blockIdx.x * blockDim.x + threadIdx.x;
    if (tid >= N_EDGES * CHUNKS) return;
    int e = tid / CHUNKS;
    int c = tid - e * CHUNKS;
    int s = __ldg(src + e);
    int d = __ldg(dst + e);
    const float4 v = *reinterpret_cast<const float4*>(g_t + (size_t)s * NC + c * 4);
    red4(g_acc + (size_t)d * NC + c * 4, v);
}

// Hop 2: g_t[dst] += g_acc[src].
__global__ void k_scatter2(const int* __restrict__ src,
                           const int* __restrict__ dst) {
    int tid = blockIdx.x * blockDim.x + threadIdx.x;
    if (tid >= N_EDGES * CHUNKS) return;
    int e = tid / CHUNKS;
    int c = tid - e * CHUNKS;
    int s = __ldg(src + e);
    int d = __ldg(dst + e);
    const float4 v = *reinterpret_cast<const float4*>(g_acc + (size_t)s * NC + c * 4);
    red4(g_t + (size_t)d * NC + c * 4, v);
}

// Between hops: acc *= norm^2 (folds end-of-hop-1 and start-of-hop-2 scalings),
// and zero g_t which becomes the hop-2 accumulator.
__global__ void k_mid() {
    int i = blockIdx.x * blockDim.x + threadIdx.x;
    if (i >= NVEC) return;
    int v = i / CHUNKS;
    float n = g_norm[v];
    float s = n * n;
    float4* pa = reinterpret_cast<float4*>(g_acc) + i;
    float4 a = *pa;
    a.x *= s; a.y *= s; a.z *= s; a.w *= s;
    *pa = a;
    reinterpret_cast<float4*>(g_t)[i] = make_float4(0, 0, 0, 0);
}

// out += norm * acc2   (acc2 lives in g_t)
__global__ void k_epi(float* __restrict__ out) {
    int i = blockIdx.x * blockDim.x + threadIdx.x;
    if (i >= NVEC) return;
    int v = i / CHUNKS;
    float n = g_norm[v];
    float4 t = reinterpret_cast<float4*>(g_t)[i];
    float4* po = reinterpret_cast<float4*>(out) + i;
    float4 o = *po;
    o.x = fmaf(n, t.x, o.x);
    o.y = fmaf(n, t.y, o.y);
    o.z = fmaf(n, t.z, o.z);
    o.w = fmaf(n, t.w, o.w);
    *po = o;
}

// ---------------------------------------------------------------------------
extern "C" void kernel_launch(void* const* d_in, const int* in_sizes, int n_in,
                              void* d_out, int out_size) {
    const float* feat  = (const float*)d_in[0];   // [50000, 96]
    const int*   src   = (const int*)  d_in[1];   // [800000]
    const int*   dst   = (const int*)  d_in[2];   // [800000]
    const float* Wsgc  = (const float*)d_in[3];   // [128, 96]
    const float* Wlin  = (const float*)d_in[4];   // [128, 96]
    const float* Wproj = (const float*)d_in[5];   // [40, 256]
    float* out = (float*)d_out;                   // [50000, 40]

    // 1) zero acc + degree buffer
    k_zero<<<(N_NODES * NC + 255) / 256, 256>>>();
    // 2) in-degree via float atomics
    k_deg<<<(N_EDGES + 255) / 256, 256>>>(dst);
    // 3) norm = deg > 0 ? deg^-1/2 : 1
    k_norm<<<(N_NODES + 255) / 256, 256>>>();
    // 4) fold projection into 40x96 matrices
    k_weights<<<dim3(NC, 2), NF>>>(Wproj, Wsgc, Wlin);
    // 5) dual GEMM: base term -> out, scaled propagation input -> g_t
    k_gemm<<<(N_NODES + GROWS - 1) / GROWS, dim3(10, 16)>>>(feat, out);
    // 6) hop 1: g_acc[dst] += g_t[src]
    k_scatter1<<<(N_EDGES * CHUNKS + 255) / 256, 256>>>(src, dst);
    // 7) rescale by norm^2, zero hop-2 accumulator
    k_mid<<<(NVEC + 255) / 256, 256>>>();
    // 8) hop 2: g_t[dst] += g_acc[src]
    k_scatter2<<<(N_EDGES * CHUNKS + 255) / 256, 256>>>(src, dst);
    // 9) out += norm * g_t
    k_epi<<<(NVEC + 255) / 256, 256>>>(out);
}